// round 5
// baseline (speedup 1.0000x reference)
#include <cuda_runtime.h>
#include <math_constants.h>

// Problem constants (fixed by the dataset: B=32, N=2048)
#define BATCH 32
#define NPTS  2048
#define TPB   256
#define NWARP (TPB / 32)           // 8 warps per block
#define BPB   16                   // blocks per batch
#define ROWS  128                  // rows per block
#define GRID  (BATCH * BPB)        // 512
#define MQ    (NPTS / NWARP)       // m-range per warp = 256
#define RPL   4                    // rows per lane (32 lanes * 4 = 128 rows)

__device__ double g_partial[GRID];
__device__ unsigned int g_count = 0;

typedef unsigned long long u64;

__device__ __forceinline__ u64 pack2(float lo, float hi) {
    u64 r;
    asm("mov.b64 %0, {%1, %2};" : "=l"(r) : "f"(lo), "f"(hi));
    return r;
}
__device__ __forceinline__ void unpack2(u64 v, float& lo, float& hi) {
    asm("mov.b64 {%0, %1}, %2;" : "=f"(lo), "=f"(hi) : "l"(v));
}
__device__ __forceinline__ u64 ffma2(u64 a, u64 b, u64 c) {
    u64 d;
    asm("fma.rn.f32x2 %0, %1, %2, %3;" : "=l"(d) : "l"(a), "l"(b), "l"(c));
    return d;
}

__device__ __forceinline__ void quat2mat(const float* __restrict__ q, float* R) {
    float w = q[0], x = q[1], y = q[2], z = q[3];
    float inv = 1.0f / sqrtf(w * w + x * x + y * y + z * z);
    w *= inv; x *= inv; y *= inv; z *= inv;
    R[0] = 1.f - 2.f * (y * y + z * z); R[1] = 2.f * (x * y - w * z); R[2] = 2.f * (x * z + w * y);
    R[3] = 2.f * (x * y + w * z);       R[4] = 1.f - 2.f * (x * x + z * z); R[5] = 2.f * (y * z - w * x);
    R[6] = 2.f * (x * z - w * y);       R[7] = 2.f * (y * z + w * x);       R[8] = 1.f - 2.f * (x * x + y * y);
}

__global__ void __launch_bounds__(TPB)
pts_loss_kernel(const float* __restrict__ q_est,
                const float* __restrict__ q_gt,
                const float* __restrict__ pts,
                const int*   __restrict__ sym,
                float* __restrict__ out)
{
    // Interleaved mapping: consecutive blocks -> different batches,
    // so sym work spreads evenly across SMs.
    const int b     = blockIdx.x % BATCH;
    const int chunk = blockIdx.x / BATCH;
    const int tid   = threadIdx.x;
    const int wid   = tid >> 5;
    const int lid   = tid & 31;

    // SoA y-table (LDS.128 yields 2 packed f32x2 operands)
    __shared__ __align__(16) float sx[NPTS];
    __shared__ __align__(16) float sy_[NPTS];
    __shared__ __align__(16) float sz[NPTS];
    __shared__ __align__(16) float sw[NPTS];
    __shared__ float s_min[NWARP][ROWS];   // per-warp partial mins
    __shared__ float s_xx[ROWS];
    __shared__ float red[TPB];

    float Re[9], Rg[9];
    quat2mat(q_est + 4 * b, Re);
    quat2mat(q_gt  + 4 * b, Rg);

    const float* __restrict__ P = pts + (size_t)b * NPTS * 3;
    const bool is_sym = (sym[b] != 0);

    float local = 0.0f;

    if (!is_sym) {
        // d_p path: ||(R_est - R_gt) @ p_n||^2, rows 0..127 on threads 0..127
        if (tid < ROWS) {
            float D[9];
            #pragma unroll
            for (int i = 0; i < 9; i++) D[i] = Re[i] - Rg[i];
            const int n = chunk * ROWS + tid;
            const float p0 = P[3 * n], p1 = P[3 * n + 1], p2 = P[3 * n + 2];
            const float e0 = D[0] * p0 + D[1] * p1 + D[2] * p2;
            const float e1 = D[3] * p0 + D[4] * p1 + D[5] * p2;
            const float e2 = D[6] * p0 + D[7] * p1 + D[8] * p2;
            local = e0 * e0 + e1 * e1 + e2 * e2;
        }
    } else {
        // Build SoA y-table: (-2*y0, -2*y1, -2*y2, yy)
        for (int m = tid; m < NPTS; m += TPB) {
            const float p0 = P[3 * m], p1 = P[3 * m + 1], p2 = P[3 * m + 2];
            const float y0 = Rg[0] * p0 + Rg[1] * p1 + Rg[2] * p2;
            const float y1 = Rg[3] * p0 + Rg[4] * p1 + Rg[5] * p2;
            const float y2 = Rg[6] * p0 + Rg[7] * p1 + Rg[8] * p2;
            sx[m]  = -2.f * y0;
            sy_[m] = -2.f * y1;
            sz[m]  = -2.f * y2;
            sw[m]  = y0 * y0 + y1 * y1 + y2 * y2;
        }
        __syncthreads();

        // Every warp covers ALL 128 rows (lane lid owns rows lid+32*r),
        // scanning only its own m-eighth [wid*256, wid*256+256).
        u64 X0[RPL], X1[RPL], X2[RPL];
        float xxv[RPL];
        #pragma unroll
        for (int r = 0; r < RPL; r++) {
            const int n = chunk * ROWS + lid + 32 * r;
            const float p0 = P[3 * n], p1 = P[3 * n + 1], p2 = P[3 * n + 2];
            const float x0 = Re[0] * p0 + Re[1] * p1 + Re[2] * p2;
            const float x1 = Re[3] * p0 + Re[4] * p1 + Re[5] * p2;
            const float x2 = Re[6] * p0 + Re[7] * p1 + Re[8] * p2;
            X0[r] = pack2(x0, x0);
            X1[r] = pack2(x1, x1);
            X2[r] = pack2(x2, x2);
            xxv[r] = x0 * x0 + x1 * x1 + x2 * x2;
        }
        if (wid == 0) {
            #pragma unroll
            for (int r = 0; r < RPL; r++) s_xx[lid + 32 * r] = xxv[r];
        }

        const int gbase = wid * (MQ / 4);   // starting ulonglong2-group for this warp
        const ulonglong2* __restrict__ SX = (const ulonglong2*)sx + gbase;
        const ulonglong2* __restrict__ SY = (const ulonglong2*)sy_ + gbase;
        const ulonglong2* __restrict__ SZ = (const ulonglong2*)sz + gbase;
        const ulonglong2* __restrict__ SW = (const ulonglong2*)sw + gbase;

        float mn[RPL][4];
        #pragma unroll
        for (int r = 0; r < RPL; r++)
            #pragma unroll
            for (int k = 0; k < 4; k++) mn[r][k] = CUDART_INF_F;

        #pragma unroll 2
        for (int g = 0; g < MQ / 4; g++) {
            const ulonglong2 vx = SX[g];
            const ulonglong2 vy = SY[g];
            const ulonglong2 vz = SZ[g];
            const ulonglong2 vw = SW[g];
            #pragma unroll
            for (int r = 0; r < RPL; r++) {
                const u64 dA = ffma2(vx.x, X0[r], ffma2(vy.x, X1[r], ffma2(vz.x, X2[r], vw.x)));
                const u64 dB = ffma2(vx.y, X0[r], ffma2(vy.y, X1[r], ffma2(vz.y, X2[r], vw.y)));
                float a, c, d, e;
                unpack2(dA, a, c);   // register renaming, no SASS
                unpack2(dB, d, e);
                mn[r][0] = fminf(mn[r][0], a);
                mn[r][1] = fminf(mn[r][1], c);
                mn[r][2] = fminf(mn[r][2], d);
                mn[r][3] = fminf(mn[r][3], e);
            }
        }

        #pragma unroll
        for (int r = 0; r < RPL; r++)
            s_min[wid][lid + 32 * r] =
                fminf(fminf(mn[r][0], mn[r][1]), fminf(mn[r][2], mn[r][3]));
        __syncthreads();

        // Thread tid (<128) finalizes row tid: combine 8 warp partials + xx
        if (tid < ROWS) {
            float mm = s_min[0][tid];
            #pragma unroll
            for (int w = 1; w < NWARP; w++) mm = fminf(mm, s_min[w][tid]);
            local = s_xx[tid] + mm;
        }
    }

    // Deterministic block reduction
    red[tid] = local;
    __syncthreads();
    #pragma unroll
    for (int s = TPB / 2; s > 0; s >>= 1) {
        if (tid < s) red[tid] += red[tid + s];
        __syncthreads();
    }

    // Fused finalize: last block reduces all partials (fixed order -> deterministic)
    __shared__ bool is_last;
    if (tid == 0) {
        g_partial[blockIdx.x] = (double)red[0];
        __threadfence();
        unsigned int c = atomicAdd(&g_count, 1u);
        is_last = (c == GRID - 1);
    }
    __syncthreads();

    if (is_last) {
        __shared__ double sd[TPB];
        double acc = 0.0;
        #pragma unroll
        for (int i = 0; i < GRID / TPB; i++)
            acc += g_partial[tid + i * TPB];
        sd[tid] = acc;
        __syncthreads();
        #pragma unroll
        for (int s = TPB / 2; s > 0; s >>= 1) {
            if (tid < s) sd[tid] += sd[tid + s];
            __syncthreads();
        }
        if (tid == 0) {
            out[0] = (float)(sd[0] / (2.0 * (double)NPTS * (double)BATCH));
            g_count = 0;   // reset for next (graph-replayed) call
        }
    }
}

extern "C" void kernel_launch(void* const* d_in, const int* in_sizes, int n_in,
                              void* d_out, int out_size)
{
    // metadata order: q_est(32x4), q_gt(32x4), T(32x3, unused), pts(32x2048x3), symmetries(32x1 int32)
    const float* q_est = (const float*)d_in[0];
    const float* q_gt  = (const float*)d_in[1];
    const float* pts   = (const float*)d_in[3];
    const int*   sym   = (const int*)d_in[4];
    float* out = (float*)d_out;

    pts_loss_kernel<<<GRID, TPB>>>(q_est, q_gt, pts, sym, out);
}

// round 6
// speedup vs baseline: 1.2522x; 1.2522x over previous
#include <cuda_runtime.h>
#include <math_constants.h>

// Problem constants (fixed by the dataset: B=32, N=2048)
#define BATCH 32
#define NPTS  2048
#define TPB   256
#define NWARP (TPB / 32)           // 8 warps per block
#define BPB   32                   // blocks (chunks) per batch
#define ROWS  64                   // rows per block
#define GRID  (BATCH * BPB)        // 1024
#define MRW   (NPTS / NWARP)       // m-range per warp = 256
#define RPL   2                    // rows per lane (32 lanes * 2 = 64 rows)
#define NG    (NPTS / 4)           // 512 groups of 4 points

__device__ double g_partial[GRID];
__device__ unsigned int g_count = 0;

typedef unsigned long long u64;

__device__ __forceinline__ u64 pack2(float lo, float hi) {
    u64 r;
    asm("mov.b64 %0, {%1, %2};" : "=l"(r) : "f"(lo), "f"(hi));
    return r;
}
__device__ __forceinline__ void unpack2(u64 v, float& lo, float& hi) {
    asm("mov.b64 {%0, %1}, %2;" : "=f"(lo), "=f"(hi) : "l"(v));
}
__device__ __forceinline__ u64 ffma2(u64 a, u64 b, u64 c) {
    u64 d;
    asm("fma.rn.f32x2 %0, %1, %2, %3;" : "=l"(d) : "l"(a), "l"(b), "l"(c));
    return d;
}

__device__ __forceinline__ void quat2mat(const float* __restrict__ q, float* R) {
    float w = q[0], x = q[1], y = q[2], z = q[3];
    float inv = 1.0f / sqrtf(w * w + x * x + y * y + z * z);
    w *= inv; x *= inv; y *= inv; z *= inv;
    R[0] = 1.f - 2.f * (y * y + z * z); R[1] = 2.f * (x * y - w * z); R[2] = 2.f * (x * z + w * y);
    R[3] = 2.f * (x * y + w * z);       R[4] = 1.f - 2.f * (x * x + z * z); R[5] = 2.f * (y * z - w * x);
    R[6] = 2.f * (x * z - w * y);       R[7] = 2.f * (y * z + w * x);       R[8] = 1.f - 2.f * (x * x + y * y);
}

__global__ void __launch_bounds__(TPB)
pts_loss_kernel(const float* __restrict__ q_est,
                const float* __restrict__ q_gt,
                const float* __restrict__ pts,
                const int*   __restrict__ sym,
                float* __restrict__ out)
{
    // Interleaved mapping: consecutive blocks -> different batches,
    // so sym work spreads evenly across SMs.
    const int b     = blockIdx.x % BATCH;
    const int chunk = blockIdx.x / BATCH;
    const int tid   = threadIdx.x;
    const int wid   = tid >> 5;
    const int lid   = tid & 31;

    // Interleaved SoA table: group g of 4 points stores
    // [x0..x3][y0..y3][z0..z3][w0..w3] in 64 contiguous bytes.
    // One base pointer per warp, 4 LDS.128 with immediate offsets per group.
    __shared__ __align__(16) float s_tab[NG * 16];
    __shared__ float s_min[NWARP][ROWS];   // per-warp partial mins
    __shared__ float s_xx[ROWS];
    __shared__ float red[TPB];

    float Re[9], Rg[9];
    quat2mat(q_est + 4 * b, Re);
    quat2mat(q_gt  + 4 * b, Rg);

    const float* __restrict__ P = pts + (size_t)b * NPTS * 3;
    const bool is_sym = (sym[b] != 0);

    float local = 0.0f;

    if (!is_sym) {
        // d_p path: ||(R_est - R_gt) @ p_n||^2, rows 0..63 on threads 0..63
        if (tid < ROWS) {
            float D[9];
            #pragma unroll
            for (int i = 0; i < 9; i++) D[i] = Re[i] - Rg[i];
            const int n = chunk * ROWS + tid;
            const float p0 = P[3 * n], p1 = P[3 * n + 1], p2 = P[3 * n + 2];
            const float e0 = D[0] * p0 + D[1] * p1 + D[2] * p2;
            const float e1 = D[3] * p0 + D[4] * p1 + D[5] * p2;
            const float e2 = D[6] * p0 + D[7] * p1 + D[8] * p2;
            local = e0 * e0 + e1 * e1 + e2 * e2;
        }
    } else {
        // Build interleaved y-table: (-2*y0, -2*y1, -2*y2, yy)
        for (int m = tid; m < NPTS; m += TPB) {
            const float p0 = P[3 * m], p1 = P[3 * m + 1], p2 = P[3 * m + 2];
            const float y0 = Rg[0] * p0 + Rg[1] * p1 + Rg[2] * p2;
            const float y1 = Rg[3] * p0 + Rg[4] * p1 + Rg[5] * p2;
            const float y2 = Rg[6] * p0 + Rg[7] * p1 + Rg[8] * p2;
            const int g = m >> 2, j = m & 3;
            float* t = s_tab + g * 16;
            t[j]      = -2.f * y0;
            t[j + 4]  = -2.f * y1;
            t[j + 8]  = -2.f * y2;
            t[j + 12] = y0 * y0 + y1 * y1 + y2 * y2;
        }
        __syncthreads();

        // Every warp covers ALL 64 rows (lane lid owns rows lid, lid+32),
        // scanning only its m-eighth [wid*256, wid*256+256).
        u64 X0[RPL], X1[RPL], X2[RPL];
        float xxv[RPL];
        #pragma unroll
        for (int r = 0; r < RPL; r++) {
            const int n = chunk * ROWS + lid + 32 * r;
            const float p0 = P[3 * n], p1 = P[3 * n + 1], p2 = P[3 * n + 2];
            const float x0 = Re[0] * p0 + Re[1] * p1 + Re[2] * p2;
            const float x1 = Re[3] * p0 + Re[4] * p1 + Re[5] * p2;
            const float x2 = Re[6] * p0 + Re[7] * p1 + Re[8] * p2;
            X0[r] = pack2(x0, x0);
            X1[r] = pack2(x1, x1);
            X2[r] = pack2(x2, x2);
            xxv[r] = x0 * x0 + x1 * x1 + x2 * x2;
        }
        if (wid == 0) {
            #pragma unroll
            for (int r = 0; r < RPL; r++) s_xx[lid + 32 * r] = xxv[r];
        }

        float mn[RPL][4];
        #pragma unroll
        for (int r = 0; r < RPL; r++)
            #pragma unroll
            for (int k = 0; k < 4; k++) mn[r][k] = CUDART_INF_F;

        const float* __restrict__ base = s_tab + (wid * (MRW / 4)) * 16;

        #pragma unroll 2
        for (int g = 0; g < MRW / 4; g++) {
            const ulonglong2* __restrict__ q = (const ulonglong2*)(base + g * 16);
            const ulonglong2 vx = q[0];
            const ulonglong2 vy = q[1];
            const ulonglong2 vz = q[2];
            const ulonglong2 vw = q[3];
            #pragma unroll
            for (int r = 0; r < RPL; r++) {
                const u64 dA = ffma2(vx.x, X0[r], ffma2(vy.x, X1[r], ffma2(vz.x, X2[r], vw.x)));
                const u64 dB = ffma2(vx.y, X0[r], ffma2(vy.y, X1[r], ffma2(vz.y, X2[r], vw.y)));
                float a, c, d, e;
                unpack2(dA, a, c);   // register renaming, no SASS
                unpack2(dB, d, e);
                mn[r][0] = fminf(mn[r][0], a);
                mn[r][1] = fminf(mn[r][1], c);
                mn[r][2] = fminf(mn[r][2], d);
                mn[r][3] = fminf(mn[r][3], e);
            }
        }

        #pragma unroll
        for (int r = 0; r < RPL; r++)
            s_min[wid][lid + 32 * r] =
                fminf(fminf(mn[r][0], mn[r][1]), fminf(mn[r][2], mn[r][3]));
        __syncthreads();

        // Thread tid (<64) finalizes row tid: combine 8 warp partials + xx
        if (tid < ROWS) {
            float mm = s_min[0][tid];
            #pragma unroll
            for (int w = 1; w < NWARP; w++) mm = fminf(mm, s_min[w][tid]);
            local = s_xx[tid] + mm;
        }
    }

    // Deterministic block reduction
    red[tid] = local;
    __syncthreads();
    #pragma unroll
    for (int s = TPB / 2; s > 0; s >>= 1) {
        if (tid < s) red[tid] += red[tid + s];
        __syncthreads();
    }

    // Fused finalize: last block reduces all partials (fixed order -> deterministic)
    __shared__ bool is_last;
    if (tid == 0) {
        g_partial[blockIdx.x] = (double)red[0];
        __threadfence();
        unsigned int c = atomicAdd(&g_count, 1u);
        is_last = (c == GRID - 1);
    }
    __syncthreads();

    if (is_last) {
        __shared__ double sd[TPB];
        double acc = 0.0;
        #pragma unroll
        for (int i = 0; i < GRID / TPB; i++)
            acc += g_partial[tid + i * TPB];
        sd[tid] = acc;
        __syncthreads();
        #pragma unroll
        for (int s = TPB / 2; s > 0; s >>= 1) {
            if (tid < s) sd[tid] += sd[tid + s];
            __syncthreads();
        }
        if (tid == 0) {
            out[0] = (float)(sd[0] / (2.0 * (double)NPTS * (double)BATCH));
            g_count = 0;   // reset for next (graph-replayed) call
        }
    }
}

extern "C" void kernel_launch(void* const* d_in, const int* in_sizes, int n_in,
                              void* d_out, int out_size)
{
    // metadata order: q_est(32x4), q_gt(32x4), T(32x3, unused), pts(32x2048x3), symmetries(32x1 int32)
    const float* q_est = (const float*)d_in[0];
    const float* q_gt  = (const float*)d_in[1];
    const float* pts   = (const float*)d_in[3];
    const int*   sym   = (const int*)d_in[4];
    float* out = (float*)d_out;

    pts_loss_kernel<<<GRID, TPB>>>(q_est, q_gt, pts, sym, out);
}